// round 4
// baseline (speedup 1.0000x reference)
#include <cuda_runtime.h>
#include <cstdint>

#define B_      16
#define C_      3
#define HW_     (512 * 512)
#define HW4_    (HW_ / 4)          /* 65536 float4 per image */
#define NCLS    64
#define NSEG    (B_ * NCLS)
#define STRIDE  32                 /* u64 elems -> 256 B bin stride */
#define NBLKX   56                 /* persistent blocks per image */
#define NBLK    (NBLKX * B_)       /* 896 ~= 6/SM x 148 SMs */
#define THREADS 128
#define NWARP   4

__device__ unsigned long long d_bins[NSEG * STRIDE];
__device__ unsigned int       d_ticket;

// global packed u64: count [44:64), sum * 2^20 in [0:44)
#define GSCALE  1048576.0f
#define GINV    (1.0f / 1048576.0f)
#define GMASK   ((1ull << 44) - 1ull)
// shared packed u32 per lane-private slot (<=40 px/slot):
//   count [26:32), sum * 2^13 in [0:26)
#define LSCALE  8192.0f
#define LCNT    (1u << 26)
#define LMASK   ((1u << 26) - 1u)
#define L2G     (GSCALE / LSCALE)  /* 128 */

__global__ void __launch_bounds__(THREADS, 6)
fused_kernel(const float* __restrict__ inp,
             const float* __restrict__ tgt,
             const int*   __restrict__ msk,
             float*       __restrict__ out)
{
    __shared__ uint32_t hist[NWARP][NCLS][32];
    __shared__ float    s_sum[2][NCLS];
    __shared__ uint32_t s_cnt[2][NCLS];

    const int t    = threadIdx.x;
    const int wid  = t >> 5;
    const int lane = t & 31;
    const int b    = blockIdx.y;

#pragma unroll
    for (int i = 0; i < (NWARP * NCLS * 32) / THREADS; i++)
        ((uint32_t*)hist)[i * THREADS + t] = 0u;
    __syncthreads();

    const float4* ip = (const float4*)(inp + (size_t)b * C_ * HW_);
    const float4* tp = (const float4*)(tgt + (size_t)b * C_ * HW_);
    const int4*   mp = (const int4*)  (msk + (size_t)b * HW_);
    uint32_t (*mybins)[32] = hist[wid];

    // persistent sweep over this image's 65536 float4 vectors
    // 56 blocks x 128 thr = 7168 lanes -> ~9.14 iterations/thread, <=40 px/slot
    for (int v = blockIdx.x * THREADS + t; v < HW4_; v += NBLKX * THREADS) {
        const float4 a0 = __ldg(ip + v);
        const float4 a1 = __ldg(ip + v + HW4_);
        const float4 a2 = __ldg(ip + v + 2 * HW4_);
        const float4 c0 = __ldg(tp + v);
        const float4 c1 = __ldg(tp + v + HW4_);
        const float4 c2 = __ldg(tp + v + 2 * HW4_);
        const int4   m  = __ldg(mp + v);

        const float w0 = fabsf(a0.x - c0.x) + fabsf(a1.x - c1.x) + fabsf(a2.x - c2.x);
        const float w1 = fabsf(a0.y - c0.y) + fabsf(a1.y - c1.y) + fabsf(a2.y - c2.y);
        const float w2 = fabsf(a0.z - c0.z) + fabsf(a1.z - c1.z) + fabsf(a2.z - c2.z);
        const float w3 = fabsf(a0.w - c0.w) + fabsf(a1.w - c1.w) + fabsf(a2.w - c2.w);

        mybins[m.x & (NCLS - 1)][lane] += LCNT + __float2uint_rn(w0 * LSCALE);
        mybins[m.y & (NCLS - 1)][lane] += LCNT + __float2uint_rn(w1 * LSCALE);
        mybins[m.z & (NCLS - 1)][lane] += LCNT + __float2uint_rn(w2 * LSCALE);
        mybins[m.w & (NCLS - 1)][lane] += LCNT + __float2uint_rn(w3 * LSCALE);
    }
    __syncthreads();

    // block flush: reduce over (warp,lane) per class, once per block
    {
        const int c = t & 63;
        const int h = t >> 6;
        float    fs = 0.0f;
        uint32_t cc = 0u;
#pragma unroll
        for (int i = 0; i < 32; i++) {
            const int l = (i + t) & 31;
            const uint32_t p0 = hist[2 * h][c][l];
            const uint32_t p1 = hist[2 * h + 1][c][l];
            cc += (p0 >> 26) + (p1 >> 26);
            fs += (float)(p0 & LMASK) + (float)(p1 & LMASK);
        }
        s_sum[h][c] = fs;
        s_cnt[h][c] = cc;
    }
    __syncthreads();

    if (t < NCLS) {
        const float    fs = s_sum[0][t] + s_sum[1][t];
        const uint32_t cc = s_cnt[0][t] + s_cnt[1][t];
        if (cc)
            atomicAdd(&d_bins[(size_t)(b * NCLS + t) * STRIDE],
                      ((unsigned long long)cc << 44) + __float2ull_rn(fs * L2G));
    }

    // last-block finalize
    __threadfence();
    __syncthreads();
    __shared__ unsigned int s_ticket;
    if (t == 0) s_ticket = atomicAdd(&d_ticket, 1u);
    __syncthreads();
    if (s_ticket != NBLK - 1) return;

    __threadfence();

    float tot = 0.0f, ws = 0.0f, mx = 0.0f;
#pragma unroll
    for (int k = 0; k < NSEG / THREADS; k++) {
        const int i = k * THREADS + t;
        const unsigned long long p = d_bins[(size_t)i * STRIDE];
        d_bins[(size_t)i * STRIDE] = 0ull;
        const float        s = (float)(p & GMASK) * GINV;
        const unsigned int c = (unsigned int)(p >> 44);
        const float avg = s / fmaxf((float)c * (float)C_, 1.0f);
        tot += s;
        ws  += s * avg;
        mx   = fmaxf(mx, avg);
    }
#pragma unroll
    for (int o = 16; o > 0; o >>= 1) {
        tot += __shfl_xor_sync(0xffffffffu, tot, o);
        ws  += __shfl_xor_sync(0xffffffffu, ws,  o);
        mx   = fmaxf(mx, __shfl_xor_sync(0xffffffffu, mx, o));
    }
    __shared__ float rtot[4], rws[4], rmx[4];
    if (lane == 0) { rtot[wid] = tot; rws[wid] = ws; rmx[wid] = mx; }
    __syncthreads();
    if (t == 0) {
        tot = rtot[0] + rtot[1] + rtot[2] + rtot[3];
        ws  = rws[0]  + rws[1]  + rws[2]  + rws[3];
        mx  = fmaxf(fmaxf(rmx[0], rmx[1]), fmaxf(rmx[2], rmx[3]));
        d_ticket = 0;
        const float N = (float)B_ * (float)C_ * (float)HW_;
        const float weighted = (mx > 0.0f) ? (ws / mx) : 0.0f;   // BETA = 1
        out[0] = (tot + weighted) / N;
    }
}

extern "C" void kernel_launch(void* const* d_in, const int* in_sizes, int n_in,
                              void* d_out, int out_size)
{
    const float* inp = (const float*)d_in[0];
    const float* tgt = (const float*)d_in[1];
    const int*   msk = (const int*)  d_in[2];
    (void)in_sizes; (void)n_in; (void)out_size;

    fused_kernel<<<dim3(NBLKX, B_), THREADS>>>(inp, tgt, msk, (float*)d_out);
}